// round 2
// baseline (speedup 1.0000x reference)
#include <cuda_runtime.h>
#include <cuda_bf16.h>
#include <math.h>

// Problem constants (from reference setup_inputs)
#define B_    16
#define LQ_   64
#define LD_   2048
#define H_    1024
#define DIM_  128
#define KPAD  2112            // static cluster bound (>= LD/1 + 1), multiple of 64
#define MQ    (B_ * LQ_)      // 1024
#define MD    (B_ * LD_)      // 32768

// -------- scratch (static device globals; no allocation allowed) --------
__device__ float        g_q_repr[MQ * DIM_];        // encoded+normalized q
__device__ float        g_d_repr[MD * DIM_];        // encoded+normalized d
__device__ float        g_pool  [B_ * KPAD * DIM_]; // segment sums -> pooled means
__device__ float        g_cnt   [B_ * KPAD];        // segment counts
__device__ int          g_kb    [B_];               // per-batch num clusters
__device__ unsigned int g_qmax  [B_ * LQ_];         // per-(b,q) running max (ordered uint)

// ---- float <-> monotonic uint mapping for atomicMax on floats ----
__device__ __forceinline__ unsigned int flipf(float f) {
    unsigned int u = __float_as_uint(f);
    return (u & 0x80000000u) ? ~u : (u | 0x80000000u);
}
__device__ __forceinline__ float unflipf(unsigned int u) {
    return (u & 0x80000000u) ? __uint_as_float(u ^ 0x80000000u)
                             : __uint_as_float(~u);
}

// ======================= 1. init scratch =======================
__global__ void init_kernel() {
    const int n = B_ * KPAD * DIM_;
    for (int i = blockIdx.x * blockDim.x + threadIdx.x; i < n;
         i += gridDim.x * blockDim.x) {
        g_pool[i] = 0.0f;
        if (i < B_ * KPAD) g_cnt[i] = 0.0f;
        if (i < B_ * LQ_)  g_qmax[i] = flipf(-1e4f);
    }
}

// ======================= 2. per-batch cluster count =======================
__global__ void kb_kernel(const int* __restrict__ d_mask,
                          const int* __restrict__ pf) {
    const int b = blockIdx.x;
    int s = 0;
    for (int i = threadIdx.x; i < LD_; i += 256)
        s += (d_mask[b * LD_ + i] > 0) ? 1 : 0;
    __shared__ int sm[8];
    for (int o = 16; o; o >>= 1) s += __shfl_down_sync(0xffffffffu, s, o);
    if ((threadIdx.x & 31) == 0) sm[threadIdx.x >> 5] = s;
    __syncthreads();
    if (threadIdx.x == 0) {
        int t = 0;
        #pragma unroll
        for (int w = 0; w < 8; w++) t += sm[w];
        if (t < 2) t = 2;
        int p = pf[0];
        if (p < 1) p = 1;
        int k = t / p + 1;
        if (k > KPAD) k = KPAD;   // safety clamp to scratch bound
        g_kb[b] = k;
    }
}

// ======================= 3. encode GEMM + bias + L2norm + mask =======================
// C[M,128] = A[M,1024] @ W[1024,128] + b ; row-L2-normalize ; * mask
// BM=64, BN=128(full), BK=16 ; 256 threads ; per-thread 4 rows x 8 cols
__global__ __launch_bounds__(256) void encode_kernel(
        const float* __restrict__ A,
        const float* __restrict__ Wm,
        const float* __restrict__ bias,
        const int*   __restrict__ mask,
        int which)   // 0 -> g_q_repr, 1 -> g_d_repr
{
    __shared__ float As[16][68];    // transposed A tile [k][row], padded
    __shared__ float Bs[16][132];   // W tile [k][n], padded
    __shared__ float red[64][17];   // row sum-of-squares partials

    float* __restrict__ out = which ? g_d_repr : g_q_repr;

    const int tid = threadIdx.x;
    const int ty  = tid >> 4;       // 0..15 -> rows ty*4..+3
    const int tx  = tid & 15;       // 0..15 -> cols {tx*4..+3} U {64+tx*4..+3}
    const int bm  = blockIdx.x * 64;

    float acc[4][8];
    #pragma unroll
    for (int i = 0; i < 4; i++)
        #pragma unroll
        for (int j = 0; j < 8; j++) acc[i][j] = 0.0f;

    const int ar = tid >> 2;          // A-load: row within tile
    const int ac = (tid & 3) * 4;     // A-load: k offset

    for (int k0 = 0; k0 < H_; k0 += 16) {
        // --- load A tile (transpose into smem) ---
        float4 av = *(const float4*)(A + (size_t)(bm + ar) * H_ + k0 + ac);
        As[ac + 0][ar] = av.x;
        As[ac + 1][ar] = av.y;
        As[ac + 2][ar] = av.z;
        As[ac + 3][ar] = av.w;
        // --- load W tile ---
        #pragma unroll
        for (int p = 0; p < 2; p++) {
            int lin  = tid + p * 256;        // 0..511
            int brow = lin >> 5;             // 0..15
            int bcol = (lin & 31) * 4;       // 0..124
            float4 bv = *(const float4*)(Wm + (size_t)(k0 + brow) * DIM_ + bcol);
            *(float4*)&Bs[brow][bcol] = bv;
        }
        __syncthreads();
        #pragma unroll
        for (int k = 0; k < 16; k++) {
            float4 a  = *(const float4*)&As[k][ty * 4];
            float4 b0 = *(const float4*)&Bs[k][tx * 4];
            float4 b1 = *(const float4*)&Bs[k][64 + tx * 4];
            float ar4[4] = {a.x, a.y, a.z, a.w};
            float br[8]  = {b0.x, b0.y, b0.z, b0.w, b1.x, b1.y, b1.z, b1.w};
            #pragma unroll
            for (int i = 0; i < 4; i++)
                #pragma unroll
                for (int j = 0; j < 8; j++)
                    acc[i][j] = fmaf(ar4[i], br[j], acc[i][j]);
        }
        __syncthreads();
    }

    // --- bias ---
    float bb[8];
    #pragma unroll
    for (int j = 0; j < 8; j++) {
        int col = (j < 4) ? (tx * 4 + j) : (64 + tx * 4 + (j - 4));
        bb[j] = bias[col];
    }
    #pragma unroll
    for (int i = 0; i < 4; i++)
        #pragma unroll
        for (int j = 0; j < 8; j++) acc[i][j] += bb[j];

    // --- row L2 norm (reduce across the 16 tx threads of each row) ---
    #pragma unroll
    for (int i = 0; i < 4; i++) {
        float s = 0.0f;
        #pragma unroll
        for (int j = 0; j < 8; j++) s = fmaf(acc[i][j], acc[i][j], s);
        red[ty * 4 + i][tx] = s;
    }
    __syncthreads();
    #pragma unroll
    for (int i = 0; i < 4; i++) {
        int row = ty * 4 + i;
        float tot = 0.0f;
        #pragma unroll
        for (int t = 0; t < 16; t++) tot += red[row][t];
        float scale = 1.0f / fmaxf(sqrtf(tot), 1e-12f);
        float mv = scale * (float)mask[bm + row];
        float4 o0, o1;
        o0.x = acc[i][0] * mv; o0.y = acc[i][1] * mv;
        o0.z = acc[i][2] * mv; o0.w = acc[i][3] * mv;
        o1.x = acc[i][4] * mv; o1.y = acc[i][5] * mv;
        o1.z = acc[i][6] * mv; o1.w = acc[i][7] * mv;
        float* orow = out + (size_t)(bm + row) * DIM_;
        *(float4*)(orow + tx * 4)      = o0;
        *(float4*)(orow + 64 + tx * 4) = o1;
    }
}

// ======================= 4. segment sums (atomic) =======================
__global__ void pool_kernel(const int* __restrict__ d_mask,
                            const int* __restrict__ labels) {
    const int row = blockIdx.x;          // 0..MD-1
    if (d_mask[row] <= 0) return;
    const int b   = row >> 11;           // row / LD_
    const int k   = g_kb[b];
    const int lab = labels[row] % k;
    const int t   = threadIdx.x;         // 0..127
    atomicAdd(&g_pool[((size_t)(b * KPAD + lab) << 7) + t],
              g_d_repr[((size_t)row << 7) + t]);
    if (t == 0) atomicAdd(&g_cnt[b * KPAD + lab], 1.0f);
}

// ======================= 5. pool finalize: mean -> L2 norm -> pad mask =======================
__global__ void finalize_kernel() {
    const int idx = blockIdx.x;          // 0..B*KPAD-1
    const int b   = idx / KPAD;
    const int kk  = idx % KPAD;
    const int t   = threadIdx.x;         // 0..127
    float c = g_cnt[idx];
    float v = g_pool[((size_t)idx << 7) + t] / fmaxf(c, 1.0f);
    float s = v * v;
    for (int o = 16; o; o >>= 1) s += __shfl_down_sync(0xffffffffu, s, o);
    __shared__ float sm[4];
    __shared__ float tot;
    if ((t & 31) == 0) sm[t >> 5] = s;
    __syncthreads();
    if (t == 0) tot = sm[0] + sm[1] + sm[2] + sm[3];
    __syncthreads();
    float scale = 1.0f / fmaxf(sqrtf(tot), 1e-12f);
    if (kk >= g_kb[b]) scale = 0.0f;     // pad mask
    g_pool[((size_t)idx << 7) + t] = v * scale;
}

// ======================= 6. sim = q . pool, running max per (b,q) =======================
// grid: (ktile, qtile, b) ; 32 q-rows x 32 clusters per block ; 256 threads (2x2 micro)
__global__ __launch_bounds__(256) void score_kernel() {
    const int b  = blockIdx.z;
    const int kb = g_kb[b];
    const int k0 = blockIdx.x * 32;
    if (k0 >= kb) return;
    const int q0 = blockIdx.y * 32;

    __shared__ float qs[128][36];   // [d][q] transposed, padded (stride 36 -> 144B)
    __shared__ float ps[128][36];   // [d][k] transposed

    const int tid = threadIdx.x;
    for (int lin = tid; lin < 32 * 128; lin += 256) {
        int r = lin >> 7, d = lin & 127;
        qs[d][r] = g_q_repr[((size_t)(b * LQ_ + q0 + r) << 7) + d];
        ps[d][r] = g_pool  [((size_t)(b * KPAD + k0 + r) << 7) + d];
    }
    __syncthreads();

    const int tq = tid >> 4;   // 0..15 -> q = q0 + tq*2 + i
    const int tk = tid & 15;   // 0..15 -> k = k0 + tk*2 + j

    float dot[2][2] = {{0.f, 0.f}, {0.f, 0.f}};
    for (int d = 0; d < 128; d++) {
        float2 qv = *(const float2*)&qs[d][tq * 2];
        float2 pv = *(const float2*)&ps[d][tk * 2];
        dot[0][0] = fmaf(qv.x, pv.x, dot[0][0]);
        dot[0][1] = fmaf(qv.x, pv.y, dot[0][1]);
        dot[1][0] = fmaf(qv.y, pv.x, dot[1][0]);
        dot[1][1] = fmaf(qv.y, pv.y, dot[1][1]);
    }

    #pragma unroll
    for (int i = 0; i < 2; i++) {
        float m = -3.4e38f;
        bool any = false;
        #pragma unroll
        for (int j = 0; j < 2; j++) {
            int kk = k0 + tk * 2 + j;
            if (kk < kb) { m = fmaxf(m, dot[i][j]); any = true; }
        }
        if (any)
            atomicMax(&g_qmax[b * LQ_ + q0 + tq * 2 + i], flipf(m));
    }
}

// ======================= 7. final reduction =======================
__global__ void final_kernel(const int* __restrict__ q_mask,
                             float* __restrict__ out) {
    const int b = blockIdx.x;
    const int t = threadIdx.x;  // 0..63
    float v = unflipf(g_qmax[b * LQ_ + t]) * (float)q_mask[b * LQ_ + t];
    for (int o = 16; o; o >>= 1) v += __shfl_down_sync(0xffffffffu, v, o);
    __shared__ float sm[2];
    if ((t & 31) == 0) sm[t >> 5] = v;
    __syncthreads();
    if (t == 0) out[b] = sm[0] + sm[1];
}

// ======================= launch =======================
extern "C" void kernel_launch(void* const* d_in, const int* in_sizes, int n_in,
                              void* d_out, int out_size) {
    const float* q_hidden = (const float*)d_in[0];
    const float* d_hidden = (const float*)d_in[1];
    const float* Wm       = (const float*)d_in[2];
    const float* bias     = (const float*)d_in[3];
    const int*   q_mask   = (const int*)  d_in[4];
    const int*   d_mask   = (const int*)  d_in[5];
    const int*   labels   = (const int*)  d_in[6];
    const int*   pf       = (const int*)  d_in[7];
    float*       out      = (float*)d_out;

    init_kernel<<<2048, 256>>>();
    kb_kernel<<<B_, 256>>>(d_mask, pf);
    encode_kernel<<<MQ / 64, 256>>>(q_hidden, Wm, bias, q_mask, 0);
    encode_kernel<<<MD / 64, 256>>>(d_hidden, Wm, bias, d_mask, 1);
    pool_kernel<<<MD, 128>>>(d_mask, labels);
    finalize_kernel<<<B_ * KPAD, 128>>>();
    dim3 sg(KPAD / 32, LQ_ / 32, B_);   // (66, 2, 16); blocks beyond k_b early-exit
    score_kernel<<<sg, 256>>>();
    final_kernel<<<B_, 64>>>(q_mask, out);
}

// round 3
// speedup vs baseline: 1.3114x; 1.3114x over previous
#include <cuda_runtime.h>
#include <cuda_bf16.h>
#include <math.h>

// Problem constants
#define B_    16
#define LQ_   64
#define LD_   2048
#define H_    1024
#define DIM_  128
#define KPAD  2112
#define MQ    (B_ * LQ_)      // 1024
#define MD    (B_ * LD_)      // 32768

// -------- scratch --------
__device__ float          g_q_repr[MQ * DIM_];
__device__ float          g_pool  [B_ * KPAD * DIM_];
__device__ float          g_cnt   [B_ * KPAD];
__device__ int            g_kb    [B_];
__device__ unsigned int   g_qmax  [B_ * LQ_];
__device__ __nv_bfloat16  g_Wt_hi [DIM_ * H_];   // [n][k]
__device__ __nv_bfloat16  g_Wt_lo [DIM_ * H_];   // [n][k]

__device__ __forceinline__ unsigned int flipf(float f) {
    unsigned int u = __float_as_uint(f);
    return (u & 0x80000000u) ? ~u : (u | 0x80000000u);
}
__device__ __forceinline__ float unflipf(unsigned int u) {
    return (u & 0x80000000u) ? __uint_as_float(u ^ 0x80000000u)
                             : __uint_as_float(~u);
}

// ======================= W split + transpose =======================
__global__ void wsplit_kernel(const float* __restrict__ Wm) {
    int i = blockIdx.x * 256 + threadIdx.x;   // 0..131071
    int k = i >> 7;
    int n = i & 127;
    float w = Wm[i];
    __nv_bfloat16 hi = __float2bfloat16(w);
    float lo = w - __bfloat162float(hi);
    g_Wt_hi[n * H_ + k] = hi;
    g_Wt_lo[n * H_ + k] = __float2bfloat16(lo);
}

// ======================= init scratch =======================
__global__ void init_kernel() {
    const int n = B_ * KPAD * DIM_;
    for (int i = blockIdx.x * blockDim.x + threadIdx.x; i < n;
         i += gridDim.x * blockDim.x) {
        g_pool[i] = 0.0f;
        if (i < B_ * KPAD) g_cnt[i] = 0.0f;
        if (i < B_ * LQ_)  g_qmax[i] = flipf(-1e4f);
    }
}

// ======================= per-batch cluster count =======================
__global__ void kb_kernel(const int* __restrict__ d_mask,
                          const int* __restrict__ pf) {
    const int b = blockIdx.x;
    int s = 0;
    for (int i = threadIdx.x; i < LD_; i += 256)
        s += (d_mask[b * LD_ + i] > 0) ? 1 : 0;
    __shared__ int sm[8];
    for (int o = 16; o; o >>= 1) s += __shfl_down_sync(0xffffffffu, s, o);
    if ((threadIdx.x & 31) == 0) sm[threadIdx.x >> 5] = s;
    __syncthreads();
    if (threadIdx.x == 0) {
        int t = 0;
        #pragma unroll
        for (int w = 0; w < 8; w++) t += sm[w];
        if (t < 2) t = 2;
        int p = pf[0];
        if (p < 1) p = 1;
        int k = t / p + 1;
        if (k > KPAD) k = KPAD;
        g_kb[b] = k;
    }
}

// ======================= encode: 3-split bf16 tensor-core GEMM =======================
// C[M,128] = A[M,1024]@W + b ; row L2-norm ; *mask ; then either store (q)
// or atomicAdd into pooled segments (d).
// BM=128, BN=128, BK=16 ; 8 warps ; warp tile 64x32 ; mma.m16n8k16
#define ASTR 24
__global__ __launch_bounds__(256, 1) void encode_kernel(
        const float* __restrict__ A,
        const float* __restrict__ bias,
        const int*   __restrict__ mask,
        const int*   __restrict__ labels,
        int which)
{
    __shared__ __nv_bfloat16 Ah[128][ASTR];
    __shared__ __nv_bfloat16 Al[128][ASTR];
    __shared__ __nv_bfloat16 Wh[128][ASTR];   // [n][k]
    __shared__ __nv_bfloat16 Wl[128][ASTR];
    __shared__ float red[128][4];
    __shared__ float scales[128];
    __shared__ int   labsm[128];

    const int tid  = threadIdx.x;
    const int warp = tid >> 5;
    const int lane = tid & 31;
    const int g    = lane >> 2;     // group 0..7
    const int tg   = lane & 3;      // 0..3
    const int wm   = warp >> 2;     // 0..1
    const int wn   = warp & 3;      // 0..3
    const int bm   = blockIdx.x * 128;

    float c[4][4][4];   // [mt][nt][reg]
    #pragma unroll
    for (int mt = 0; mt < 4; mt++)
        #pragma unroll
        for (int nt = 0; nt < 4; nt++)
            #pragma unroll
            for (int r = 0; r < 4; r++) c[mt][nt][r] = 0.0f;

    // A-load mapping: 2 threads per row, 8 k each
    const int arow = tid >> 1;
    const int asub = (tid & 1) * 8;
    const float* aptr = A + (size_t)(bm + arow) * H_ + asub;
    // W-load mapping: 2 threads per n, 8 k each
    const int wrow = tid >> 1;
    const int wsub = (tid & 1) * 8;

    for (int k0 = 0; k0 < H_; k0 += 16) {
        // --- A tile: fp32 -> hi/lo bf16 ---
        float4 a0 = *(const float4*)(aptr + k0);
        float4 a1 = *(const float4*)(aptr + k0 + 4);
        float av[8] = {a0.x, a0.y, a0.z, a0.w, a1.x, a1.y, a1.z, a1.w};
        __nv_bfloat162 hi4[4], lo4[4];
        #pragma unroll
        for (int j = 0; j < 4; j++) {
            __nv_bfloat16 h0 = __float2bfloat16(av[2 * j]);
            __nv_bfloat16 h1 = __float2bfloat16(av[2 * j + 1]);
            hi4[j] = __nv_bfloat162(h0, h1);
            lo4[j] = __nv_bfloat162(
                __float2bfloat16(av[2 * j]     - __bfloat162float(h0)),
                __float2bfloat16(av[2 * j + 1] - __bfloat162float(h1)));
        }
        #pragma unroll
        for (int j = 0; j < 4; j++) {
            *(__nv_bfloat162*)&Ah[arow][asub + 2 * j] = hi4[j];
            *(__nv_bfloat162*)&Al[arow][asub + 2 * j] = lo4[j];
        }
        // --- W tile: bf16 copy from pre-split transposed global ---
        uint4 wh = *(const uint4*)(g_Wt_hi + (size_t)wrow * H_ + k0 + wsub);
        uint4 wl = *(const uint4*)(g_Wt_lo + (size_t)wrow * H_ + k0 + wsub);
        *(uint4*)&Wh[wrow][wsub] = wh;
        *(uint4*)&Wl[wrow][wsub] = wl;
        __syncthreads();

        // --- fragments ---
        unsigned int afh[4][4], afl[4][4], bfh[4][2], bfl[4][2];
        #pragma unroll
        for (int mt = 0; mt < 4; mt++) {
            int r0 = wm * 64 + mt * 16 + g;
            afh[mt][0] = *(const unsigned int*)&Ah[r0][2 * tg];
            afh[mt][1] = *(const unsigned int*)&Ah[r0 + 8][2 * tg];
            afh[mt][2] = *(const unsigned int*)&Ah[r0][2 * tg + 8];
            afh[mt][3] = *(const unsigned int*)&Ah[r0 + 8][2 * tg + 8];
            afl[mt][0] = *(const unsigned int*)&Al[r0][2 * tg];
            afl[mt][1] = *(const unsigned int*)&Al[r0 + 8][2 * tg];
            afl[mt][2] = *(const unsigned int*)&Al[r0][2 * tg + 8];
            afl[mt][3] = *(const unsigned int*)&Al[r0 + 8][2 * tg + 8];
        }
        #pragma unroll
        for (int nt = 0; nt < 4; nt++) {
            int n0 = wn * 32 + nt * 8 + g;
            bfh[nt][0] = *(const unsigned int*)&Wh[n0][2 * tg];
            bfh[nt][1] = *(const unsigned int*)&Wh[n0][2 * tg + 8];
            bfl[nt][0] = *(const unsigned int*)&Wl[n0][2 * tg];
            bfl[nt][1] = *(const unsigned int*)&Wl[n0][2 * tg + 8];
        }

        #pragma unroll
        for (int mt = 0; mt < 4; mt++)
            #pragma unroll
            for (int nt = 0; nt < 4; nt++) {
                float* cc = c[mt][nt];
                asm volatile(
                    "mma.sync.aligned.m16n8k16.row.col.f32.bf16.bf16.f32 "
                    "{%0,%1,%2,%3}, {%4,%5,%6,%7}, {%8,%9}, {%0,%1,%2,%3};"
                    : "+f"(cc[0]), "+f"(cc[1]), "+f"(cc[2]), "+f"(cc[3])
                    : "r"(afh[mt][0]), "r"(afh[mt][1]), "r"(afh[mt][2]), "r"(afh[mt][3]),
                      "r"(bfh[nt][0]), "r"(bfh[nt][1]));
                asm volatile(
                    "mma.sync.aligned.m16n8k16.row.col.f32.bf16.bf16.f32 "
                    "{%0,%1,%2,%3}, {%4,%5,%6,%7}, {%8,%9}, {%0,%1,%2,%3};"
                    : "+f"(cc[0]), "+f"(cc[1]), "+f"(cc[2]), "+f"(cc[3])
                    : "r"(afh[mt][0]), "r"(afh[mt][1]), "r"(afh[mt][2]), "r"(afh[mt][3]),
                      "r"(bfl[nt][0]), "r"(bfl[nt][1]));
                asm volatile(
                    "mma.sync.aligned.m16n8k16.row.col.f32.bf16.bf16.f32 "
                    "{%0,%1,%2,%3}, {%4,%5,%6,%7}, {%8,%9}, {%0,%1,%2,%3};"
                    : "+f"(cc[0]), "+f"(cc[1]), "+f"(cc[2]), "+f"(cc[3])
                    : "r"(afl[mt][0]), "r"(afl[mt][1]), "r"(afl[mt][2]), "r"(afl[mt][3]),
                      "r"(bfh[nt][0]), "r"(bfh[nt][1]));
            }
        __syncthreads();
    }

    // --- bias add ---
    #pragma unroll
    for (int nt = 0; nt < 4; nt++) {
        int bcol = wn * 32 + nt * 8 + 2 * tg;
        float2 bb = *(const float2*)&bias[bcol];
        #pragma unroll
        for (int mt = 0; mt < 4; mt++) {
            c[mt][nt][0] += bb.x; c[mt][nt][1] += bb.y;
            c[mt][nt][2] += bb.x; c[mt][nt][3] += bb.y;
        }
    }

    // --- row sum-of-squares, reduce across quad + warp-columns ---
    #pragma unroll
    for (int mt = 0; mt < 4; mt++) {
        float slo = 0.0f, shi = 0.0f;
        #pragma unroll
        for (int nt = 0; nt < 4; nt++) {
            slo = fmaf(c[mt][nt][0], c[mt][nt][0], slo);
            slo = fmaf(c[mt][nt][1], c[mt][nt][1], slo);
            shi = fmaf(c[mt][nt][2], c[mt][nt][2], shi);
            shi = fmaf(c[mt][nt][3], c[mt][nt][3], shi);
        }
        slo += __shfl_xor_sync(0xffffffffu, slo, 1);
        slo += __shfl_xor_sync(0xffffffffu, slo, 2);
        shi += __shfl_xor_sync(0xffffffffu, shi, 1);
        shi += __shfl_xor_sync(0xffffffffu, shi, 2);
        if (tg == 0) {
            red[wm * 64 + mt * 16 + g][wn]     = slo;
            red[wm * 64 + mt * 16 + g + 8][wn] = shi;
        }
    }
    __syncthreads();

    if (tid < 128) {
        float tot = red[tid][0] + red[tid][1] + red[tid][2] + red[tid][3];
        float scale = 1.0f / fmaxf(sqrtf(tot), 1e-12f);
        scales[tid] = scale * (float)mask[bm + tid];
        if (which) {
            int r = bm + tid;
            int b = r >> 11;
            labsm[tid] = (b * KPAD + labels[r] % g_kb[b]) * DIM_;
        }
    }
    __syncthreads();

    if (which == 0) {
        // q: store normalized rows
        #pragma unroll
        for (int mt = 0; mt < 4; mt++) {
            int rl = wm * 64 + mt * 16 + g;
            float sl = scales[rl], sh = scales[rl + 8];
            #pragma unroll
            for (int nt = 0; nt < 4; nt++) {
                int col = wn * 32 + nt * 8 + 2 * tg;
                float2 v0 = make_float2(c[mt][nt][0] * sl, c[mt][nt][1] * sl);
                float2 v1 = make_float2(c[mt][nt][2] * sh, c[mt][nt][3] * sh);
                *(float2*)&g_q_repr[(size_t)(bm + rl) * DIM_ + col]     = v0;
                *(float2*)&g_q_repr[(size_t)(bm + rl + 8) * DIM_ + col] = v1;
            }
        }
    } else {
        // d: fused segment-sum pooling
        #pragma unroll
        for (int mt = 0; mt < 4; mt++) {
            int rl = wm * 64 + mt * 16 + g;
            float sl = scales[rl], sh = scales[rl + 8];
            int dl = labsm[rl], dh = labsm[rl + 8];
            #pragma unroll
            for (int nt = 0; nt < 4; nt++) {
                int col = wn * 32 + nt * 8 + 2 * tg;
                atomicAdd(&g_pool[dl + col],     c[mt][nt][0] * sl);
                atomicAdd(&g_pool[dl + col + 1], c[mt][nt][1] * sl);
                atomicAdd(&g_pool[dh + col],     c[mt][nt][2] * sh);
                atomicAdd(&g_pool[dh + col + 1], c[mt][nt][3] * sh);
            }
        }
    }
}

// ======================= segment counts =======================
__global__ void cnt_kernel(const int* __restrict__ d_mask,
                           const int* __restrict__ labels) {
    int row = blockIdx.x * 256 + threadIdx.x;
    if (row >= MD) return;
    if (d_mask[row] <= 0) return;
    int b = row >> 11;
    atomicAdd(&g_cnt[b * KPAD + labels[row] % g_kb[b]], 1.0f);
}

// ======================= pool finalize (active clusters only) =======================
__global__ void finalize_kernel() {
    const int idx = blockIdx.x;
    const int b   = idx / KPAD;
    const int kk  = idx % KPAD;
    if (kk >= g_kb[b]) return;           // pads stay zero / never read
    const int t = threadIdx.x;
    float cdiv = 1.0f / fmaxf(g_cnt[idx], 1.0f);
    float v = g_pool[((size_t)idx << 7) + t] * cdiv;
    float s = v * v;
    for (int o = 16; o; o >>= 1) s += __shfl_down_sync(0xffffffffu, s, o);
    __shared__ float sm[4];
    __shared__ float tot;
    if ((t & 31) == 0) sm[t >> 5] = s;
    __syncthreads();
    if (t == 0) tot = sm[0] + sm[1] + sm[2] + sm[3];
    __syncthreads();
    float scale = 1.0f / fmaxf(sqrtf(tot), 1e-12f);
    g_pool[((size_t)idx << 7) + t] = v * scale;
}

// ======================= sim + running max =======================
__global__ __launch_bounds__(256) void score_kernel() {
    const int b  = blockIdx.z;
    const int kb = g_kb[b];
    const int k0 = blockIdx.x * 32;
    if (k0 >= kb) return;
    const int q0 = blockIdx.y * 32;

    __shared__ float qs[128][36];
    __shared__ float ps[128][36];

    const int tid = threadIdx.x;
    for (int lin = tid; lin < 32 * 128; lin += 256) {
        int r = lin >> 7, d = lin & 127;
        qs[d][r] = g_q_repr[((size_t)(b * LQ_ + q0 + r) << 7) + d];
        ps[d][r] = g_pool  [((size_t)(b * KPAD + k0 + r) << 7) + d];
    }
    __syncthreads();

    const int tq = tid >> 4;
    const int tk = tid & 15;

    float dot[2][2] = {{0.f, 0.f}, {0.f, 0.f}};
    for (int d = 0; d < 128; d++) {
        float2 qv = *(const float2*)&qs[d][tq * 2];
        float2 pv = *(const float2*)&ps[d][tk * 2];
        dot[0][0] = fmaf(qv.x, pv.x, dot[0][0]);
        dot[0][1] = fmaf(qv.x, pv.y, dot[0][1]);
        dot[1][0] = fmaf(qv.y, pv.x, dot[1][0]);
        dot[1][1] = fmaf(qv.y, pv.y, dot[1][1]);
    }

    #pragma unroll
    for (int i = 0; i < 2; i++) {
        float m = -3.4e38f;
        bool any = false;
        #pragma unroll
        for (int j = 0; j < 2; j++) {
            int kk = k0 + tk * 2 + j;
            if (kk < kb) { m = fmaxf(m, dot[i][j]); any = true; }
        }
        if (any)
            atomicMax(&g_qmax[b * LQ_ + q0 + tq * 2 + i], flipf(m));
    }
}

// ======================= final reduction =======================
__global__ void final_kernel(const int* __restrict__ q_mask,
                             float* __restrict__ out) {
    const int b = blockIdx.x;
    const int t = threadIdx.x;
    float v = unflipf(g_qmax[b * LQ_ + t]) * (float)q_mask[b * LQ_ + t];
    for (int o = 16; o; o >>= 1) v += __shfl_down_sync(0xffffffffu, v, o);
    __shared__ float sm[2];
    if ((t & 31) == 0) sm[t >> 5] = v;
    __syncthreads();
    if (t == 0) out[b] = sm[0] + sm[1];
}

// ======================= launch =======================
extern "C" void kernel_launch(void* const* d_in, const int* in_sizes, int n_in,
                              void* d_out, int out_size) {
    const float* q_hidden = (const float*)d_in[0];
    const float* d_hidden = (const float*)d_in[1];
    const float* Wm       = (const float*)d_in[2];
    const float* bias     = (const float*)d_in[3];
    const int*   q_mask   = (const int*)  d_in[4];
    const int*   d_mask   = (const int*)  d_in[5];
    const int*   labels   = (const int*)  d_in[6];
    const int*   pf       = (const int*)  d_in[7];
    float*       out      = (float*)d_out;

    wsplit_kernel<<<512, 256>>>(Wm);
    init_kernel<<<2048, 256>>>();
    kb_kernel<<<B_, 256>>>(d_mask, pf);
    encode_kernel<<<MQ / 128, 256>>>(q_hidden, bias, q_mask, nullptr, 0);
    encode_kernel<<<MD / 128, 256>>>(d_hidden, bias, d_mask, labels, 1);
    cnt_kernel<<<MD / 256, 256>>>(d_mask, labels);
    finalize_kernel<<<B_ * KPAD, 128>>>();
    dim3 sg(KPAD / 32, LQ_ / 32, B_);
    score_kernel<<<sg, 256>>>();
    final_kernel<<<B_, 64>>>(q_mask, out);
}

// round 6
// speedup vs baseline: 1.5667x; 1.1947x over previous
#include <cuda_runtime.h>
#include <cuda_bf16.h>
#include <math.h>
#include <cstdint>

// Problem constants
#define B_    16
#define LQ_   64
#define LD_   2048
#define H_    1024
#define DIM_  128
#define KPAD  2112
#define MQ    (B_ * LQ_)      // 1024
#define MD    (B_ * LD_)      // 32768
#define QBLK  (MQ / 128)      // 8
#define DBLK  (MD / 128)      // 256

// -------- scratch --------
__device__ float          g_q_repr[MQ * DIM_];
__device__ float          g_pool  [B_ * KPAD * DIM_];
__device__ float          g_cnt   [B_ * KPAD];
__device__ int            g_kb    [B_];
__device__ unsigned int   g_qmax  [B_ * LQ_];
__device__ __nv_bfloat16  g_Wt_hi [DIM_ * H_];   // [n][k]
__device__ __nv_bfloat16  g_Wt_lo [DIM_ * H_];   // [n][k]

__device__ __forceinline__ unsigned int flipf(float f) {
    unsigned int u = __float_as_uint(f);
    return (u & 0x80000000u) ? ~u : (u | 0x80000000u);
}
__device__ __forceinline__ float unflipf(unsigned int u) {
    return (u & 0x80000000u) ? __uint_as_float(u ^ 0x80000000u)
                             : __uint_as_float(~u);
}

__device__ __forceinline__ uint32_t smem_to_u32(const void* p) {
    uint32_t a;
    asm("{ .reg .u64 t; cvta.to.shared.u64 t, %1; cvt.u32.u64 %0, t; }"
        : "=r"(a) : "l"(p));
    return a;
}
#define CP_ASYNC16(dst, src) \
    asm volatile("cp.async.cg.shared.global [%0], [%1], 16;" \
                 :: "r"((uint32_t)(dst)), "l"(src) : "memory")
#define CP_COMMIT() asm volatile("cp.async.commit_group;" ::: "memory")
#define CP_WAIT0()  asm volatile("cp.async.wait_group 0;" ::: "memory")
#define STS128U(addr, a, b, c, d) \
    asm volatile("st.shared.v4.b32 [%0], {%1,%2,%3,%4};" \
                 :: "r"((uint32_t)(addr)), "r"(a), "r"(b), "r"(c), "r"(d) : "memory")

// ======================= W split + transpose =======================
__global__ void wsplit_kernel(const float* __restrict__ Wm) {
    int i = blockIdx.x * 256 + threadIdx.x;   // 0..131071
    int k = i >> 7;
    int n = i & 127;
    float w = Wm[i];
    __nv_bfloat16 hi = __float2bfloat16(w);
    float lo = w - __bfloat162float(hi);
    g_Wt_hi[n * H_ + k] = hi;
    g_Wt_lo[n * H_ + k] = __float2bfloat16(lo);
}

// ======================= init scratch =======================
__global__ void init_kernel() {
    const int n = B_ * KPAD * DIM_;
    for (int i = blockIdx.x * blockDim.x + threadIdx.x; i < n;
         i += gridDim.x * blockDim.x) {
        g_pool[i] = 0.0f;
        if (i < B_ * KPAD) g_cnt[i] = 0.0f;
        if (i < B_ * LQ_)  g_qmax[i] = flipf(-1e4f);
    }
}

// ======================= per-batch cluster count =======================
__global__ void kb_kernel(const int* __restrict__ d_mask,
                          const int* __restrict__ pf) {
    const int b = blockIdx.x;
    int s = 0;
    for (int i = threadIdx.x; i < LD_; i += 256)
        s += (d_mask[b * LD_ + i] > 0) ? 1 : 0;
    __shared__ int sm[8];
    for (int o = 16; o; o >>= 1) s += __shfl_down_sync(0xffffffffu, s, o);
    if ((threadIdx.x & 31) == 0) sm[threadIdx.x >> 5] = s;
    __syncthreads();
    if (threadIdx.x == 0) {
        int t = 0;
        #pragma unroll
        for (int w = 0; w < 8; w++) t += sm[w];
        if (t < 2) t = 2;
        int p = pf[0];
        if (p < 1) p = 1;
        int k = t / p + 1;
        if (k > KPAD) k = KPAD;
        g_kb[b] = k;
    }
}

// ======================= fused encode (mma.sync, pipelined) =======================
// grid = 264: blocks [0,8) -> q rows, [8,264) -> d rows.
// BM=128, BN=128, BK=16, 8 warps, warp tile 64x32, mma.m16n8k16, 3-split bf16.
#define ASTR    24                     // smem row stride in bf16 elems
#define ARR_B   (128 * ASTR * 2)       // 6144 bytes per array
#define STAGE_B (4 * ARR_B)            // Ah, Al, Wh, Wl = 24576
#define SMEM_DYN (2 * STAGE_B)         // 49152

__global__ __launch_bounds__(256, 1) void encode_kernel(
        const float* __restrict__ q_hidden,
        const float* __restrict__ d_hidden,
        const float* __restrict__ bias,
        const int*   __restrict__ q_mask,
        const int*   __restrict__ d_mask,
        const int*   __restrict__ labels)
{
    extern __shared__ char smem[];
    __shared__ float red[128][4];
    __shared__ float scales[128];
    __shared__ int   labsm[128];

    const uint32_t sb32 = smem_to_u32(smem);
    const int tid  = threadIdx.x;
    const int warp = tid >> 5;
    const int lane = tid & 31;
    const int g    = lane >> 2;
    const int tg   = lane & 3;
    const int wm   = warp >> 2;
    const int wn   = warp & 3;

    const bool is_q = (blockIdx.x < QBLK);
    const float* A    = is_q ? q_hidden : d_hidden;
    const int*   mask = is_q ? q_mask   : d_mask;
    const int    bm   = is_q ? (int)blockIdx.x * 128 : ((int)blockIdx.x - QBLK) * 128;

    float c[4][4][4];
    #pragma unroll
    for (int mt = 0; mt < 4; mt++)
        #pragma unroll
        for (int nt = 0; nt < 4; nt++)
            #pragma unroll
            for (int r = 0; r < 4; r++) c[mt][nt][r] = 0.0f;

    // per-thread load mapping: 2 threads per row, 8 elems each
    const int arow = tid >> 1;
    const int half = (tid & 1);            // 0/1 -> elems 0..7 / 8..15
    const float* aptr = A + (size_t)(bm + arow) * H_ + half * 8;
    const __nv_bfloat16* whp = g_Wt_hi + (size_t)arow * H_ + half * 8;
    const __nv_bfloat16* wlp = g_Wt_lo + (size_t)arow * H_ + half * 8;
    const uint32_t sts_off = (uint32_t)(arow * (ASTR * 2) + half * 16);

    // stage base offsets
    uint32_t ah_s[2], al_s[2], wh_s[2], wl_s[2];
    #pragma unroll
    for (int s = 0; s < 2; s++) {
        ah_s[s] = sb32 + s * STAGE_B;
        al_s[s] = ah_s[s] + ARR_B;
        wh_s[s] = ah_s[s] + 2 * ARR_B;
        wl_s[s] = ah_s[s] + 3 * ARR_B;
    }

    // ---- convert + STS helper (A fp32x8 -> hi/lo bf16) ----
    auto put_a = [&](int s, float4 a0, float4 a1) {
        float av[8] = {a0.x, a0.y, a0.z, a0.w, a1.x, a1.y, a1.z, a1.w};
        uint32_t hw[4], lw[4];
        #pragma unroll
        for (int q = 0; q < 4; q++) {
            __nv_bfloat16 h0 = __float2bfloat16(av[2 * q]);
            __nv_bfloat16 h1 = __float2bfloat16(av[2 * q + 1]);
            __nv_bfloat162 hp(h0, h1);
            __nv_bfloat162 lp(__float2bfloat16(av[2 * q]     - __bfloat162float(h0)),
                              __float2bfloat16(av[2 * q + 1] - __bfloat162float(h1)));
            hw[q] = *(uint32_t*)&hp;
            lw[q] = *(uint32_t*)&lp;
        }
        STS128U(ah_s[s] + sts_off, hw[0], hw[1], hw[2], hw[3]);
        STS128U(al_s[s] + sts_off, lw[0], lw[1], lw[2], lw[3]);
    };

    // ---- preload stage 0 ----
    {
        CP_ASYNC16(wh_s[0] + sts_off, whp);
        CP_ASYNC16(wl_s[0] + sts_off, wlp);
        CP_COMMIT();
        float4 a0 = *(const float4*)aptr;
        float4 a1 = *(const float4*)(aptr + 4);
        put_a(0, a0, a1);
        CP_WAIT0();
    }
    __syncthreads();

    const int NIT = H_ / 16;   // 64
    for (int it = 0; it < NIT; it++) {
        const int cur = it & 1;
        const int nxt = cur ^ 1;
        float4 na0, na1;
        if (it + 1 < NIT) {
            const int ko = (it + 1) * 16;
            CP_ASYNC16(wh_s[nxt] + sts_off, whp + ko);
            CP_ASYNC16(wl_s[nxt] + sts_off, wlp + ko);
            CP_COMMIT();
            na0 = *(const float4*)(aptr + ko);
            na1 = *(const float4*)(aptr + ko + 4);
        }

        // ---- compute on stage cur ----
        const __nv_bfloat16* Ah = (const __nv_bfloat16*)(smem + cur * STAGE_B);
        const __nv_bfloat16* Al = (const __nv_bfloat16*)(smem + cur * STAGE_B + ARR_B);
        const __nv_bfloat16* Wh = (const __nv_bfloat16*)(smem + cur * STAGE_B + 2 * ARR_B);
        const __nv_bfloat16* Wl = (const __nv_bfloat16*)(smem + cur * STAGE_B + 3 * ARR_B);

        unsigned int afh[4][4], afl[4][4], bfh[4][2], bfl[4][2];
        #pragma unroll
        for (int mt = 0; mt < 4; mt++) {
            int r0 = wm * 64 + mt * 16 + g;
            afh[mt][0] = *(const unsigned int*)&Ah[r0 * ASTR + 2 * tg];
            afh[mt][1] = *(const unsigned int*)&Ah[(r0 + 8) * ASTR + 2 * tg];
            afh[mt][2] = *(const unsigned int*)&Ah[r0 * ASTR + 2 * tg + 8];
            afh[mt][3] = *(const unsigned int*)&Ah[(r0 + 8) * ASTR + 2 * tg + 8];
            afl[mt][0] = *(const unsigned int*)&Al[r0 * ASTR + 2 * tg];
            afl[mt][1] = *(const unsigned int*)&Al[(r0 + 8) * ASTR + 2 * tg];
            afl[mt][2] = *(const unsigned int*)&Al[r0 * ASTR + 2 * tg + 8];
            afl[mt][3] = *(const unsigned int*)&Al[(r0 + 8) * ASTR + 2 * tg + 8];
        }
        #pragma unroll
        for (int nt = 0; nt < 4; nt++) {
            int n0 = wn * 32 + nt * 8 + g;
            bfh[nt][0] = *(const unsigned int*)&Wh[n0 * ASTR + 2 * tg];
            bfh[nt][1] = *(const unsigned int*)&Wh[n0 * ASTR + 2 * tg + 8];
            bfl[nt][0] = *(const unsigned int*)&Wl[n0 * ASTR + 2 * tg];
            bfl[nt][1] = *(const unsigned int*)&Wl[n0 * ASTR + 2 * tg + 8];
        }
        #pragma unroll
        for (int mt = 0; mt < 4; mt++)
            #pragma unroll
            for (int nt = 0; nt < 4; nt++) {
                float* cc = c[mt][nt];
                asm volatile(
                    "mma.sync.aligned.m16n8k16.row.col.f32.bf16.bf16.f32 "
                    "{%0,%1,%2,%3}, {%4,%5,%6,%7}, {%8,%9}, {%0,%1,%2,%3};"
                    : "+f"(cc[0]), "+f"(cc[1]), "+f"(cc[2]), "+f"(cc[3])
                    : "r"(afh[mt][0]), "r"(afh[mt][1]), "r"(afh[mt][2]), "r"(afh[mt][3]),
                      "r"(bfh[nt][0]), "r"(bfh[nt][1]));
                asm volatile(
                    "mma.sync.aligned.m16n8k16.row.col.f32.bf16.bf16.f32 "
                    "{%0,%1,%2,%3}, {%4,%5,%6,%7}, {%8,%9}, {%0,%1,%2,%3};"
                    : "+f"(cc[0]), "+f"(cc[1]), "+f"(cc[2]), "+f"(cc[3])
                    : "r"(afh[mt][0]), "r"(afh[mt][1]), "r"(afh[mt][2]), "r"(afh[mt][3]),
                      "r"(bfl[nt][0]), "r"(bfl[nt][1]));
                asm volatile(
                    "mma.sync.aligned.m16n8k16.row.col.f32.bf16.bf16.f32 "
                    "{%0,%1,%2,%3}, {%4,%5,%6,%7}, {%8,%9}, {%0,%1,%2,%3};"
                    : "+f"(cc[0]), "+f"(cc[1]), "+f"(cc[2]), "+f"(cc[3])
                    : "r"(afl[mt][0]), "r"(afl[mt][1]), "r"(afl[mt][2]), "r"(afl[mt][3]),
                      "r"(bfh[nt][0]), "r"(bfh[nt][1]));
            }

        if (it + 1 < NIT) {
            put_a(nxt, na0, na1);
            CP_WAIT0();
        }
        __syncthreads();
    }

    // ---- bias add ----
    #pragma unroll
    for (int nt = 0; nt < 4; nt++) {
        int bcol = wn * 32 + nt * 8 + 2 * tg;
        float2 bb = *(const float2*)&bias[bcol];
        #pragma unroll
        for (int mt = 0; mt < 4; mt++) {
            c[mt][nt][0] += bb.x; c[mt][nt][1] += bb.y;
            c[mt][nt][2] += bb.x; c[mt][nt][3] += bb.y;
        }
    }

    // ---- row sum-of-squares ----
    #pragma unroll
    for (int mt = 0; mt < 4; mt++) {
        float slo = 0.0f, shi = 0.0f;
        #pragma unroll
        for (int nt = 0; nt < 4; nt++) {
            slo = fmaf(c[mt][nt][0], c[mt][nt][0], slo);
            slo = fmaf(c[mt][nt][1], c[mt][nt][1], slo);
            shi = fmaf(c[mt][nt][2], c[mt][nt][2], shi);
            shi = fmaf(c[mt][nt][3], c[mt][nt][3], shi);
        }
        slo += __shfl_xor_sync(0xffffffffu, slo, 1);
        slo += __shfl_xor_sync(0xffffffffu, slo, 2);
        shi += __shfl_xor_sync(0xffffffffu, shi, 1);
        shi += __shfl_xor_sync(0xffffffffu, shi, 2);
        if (tg == 0) {
            red[wm * 64 + mt * 16 + g][wn]     = slo;
            red[wm * 64 + mt * 16 + g + 8][wn] = shi;
        }
    }
    __syncthreads();

    if (tid < 128) {
        float tot = red[tid][0] + red[tid][1] + red[tid][2] + red[tid][3];
        float scale = 1.0f / fmaxf(sqrtf(tot), 1e-12f);
        scales[tid] = scale * (float)mask[bm + tid];
        if (!is_q) {
            int r = bm + tid;
            int b = r >> 11;
            labsm[tid] = (b * KPAD + labels[r] % g_kb[b]) * DIM_;
        }
    }
    __syncthreads();

    if (is_q) {
        #pragma unroll
        for (int mt = 0; mt < 4; mt++) {
            int rl = wm * 64 + mt * 16 + g;
            float sl = scales[rl], sh = scales[rl + 8];
            #pragma unroll
            for (int nt = 0; nt < 4; nt++) {
                int col = wn * 32 + nt * 8 + 2 * tg;
                float2 v0 = make_float2(c[mt][nt][0] * sl, c[mt][nt][1] * sl);
                float2 v1 = make_float2(c[mt][nt][2] * sh, c[mt][nt][3] * sh);
                *(float2*)&g_q_repr[(size_t)(bm + rl) * DIM_ + col]     = v0;
                *(float2*)&g_q_repr[(size_t)(bm + rl + 8) * DIM_ + col] = v1;
            }
        }
    } else {
        #pragma unroll
        for (int mt = 0; mt < 4; mt++) {
            int rl = wm * 64 + mt * 16 + g;
            float sl = scales[rl], sh = scales[rl + 8];
            int dl = labsm[rl], dh = labsm[rl + 8];
            #pragma unroll
            for (int nt = 0; nt < 4; nt++) {
                int col = wn * 32 + nt * 8 + 2 * tg;
                atomicAdd(&g_pool[dl + col],     c[mt][nt][0] * sl);
                atomicAdd(&g_pool[dl + col + 1], c[mt][nt][1] * sl);
                atomicAdd(&g_pool[dh + col],     c[mt][nt][2] * sh);
                atomicAdd(&g_pool[dh + col + 1], c[mt][nt][3] * sh);
            }
        }
    }
}

// ======================= segment counts =======================
__global__ void cnt_kernel(const int* __restrict__ d_mask,
                           const int* __restrict__ labels) {
    int row = blockIdx.x * 256 + threadIdx.x;
    if (row >= MD) return;
    if (d_mask[row] <= 0) return;
    int b = row >> 11;
    atomicAdd(&g_cnt[b * KPAD + labels[row] % g_kb[b]], 1.0f);
}

// ======================= pool finalize =======================
__global__ void finalize_kernel() {
    const int idx = blockIdx.x;
    const int b   = idx / KPAD;
    const int kk  = idx % KPAD;
    if (kk >= g_kb[b]) return;
    const int t = threadIdx.x;
    float cdiv = 1.0f / fmaxf(g_cnt[idx], 1.0f);
    float v = g_pool[((size_t)idx << 7) + t] * cdiv;
    float s = v * v;
    for (int o = 16; o; o >>= 1) s += __shfl_down_sync(0xffffffffu, s, o);
    __shared__ float sm[4];
    __shared__ float tot;
    if ((t & 31) == 0) sm[t >> 5] = s;
    __syncthreads();
    if (t == 0) tot = sm[0] + sm[1] + sm[2] + sm[3];
    __syncthreads();
    float scale = 1.0f / fmaxf(sqrtf(tot), 1e-12f);
    g_pool[((size_t)idx << 7) + t] = v * scale;
}

// ======================= sim + running max =======================
__global__ __launch_bounds__(256) void score_kernel() {
    const int b  = blockIdx.z;
    const int kb = g_kb[b];
    const int k0 = blockIdx.x * 32;
    if (k0 >= kb) return;
    const int q0 = blockIdx.y * 32;

    __shared__ float qs[128][36];
    __shared__ float ps[128][36];

    const int tid = threadIdx.x;
    for (int lin = tid; lin < 32 * 128; lin += 256) {
        int r = lin >> 7, d = lin & 127;
        qs[d][r] = g_q_repr[((size_t)(b * LQ_ + q0 + r) << 7) + d];
        ps[d][r] = g_pool  [((size_t)(b * KPAD + k0 + r) << 7) + d];
    }
    __syncthreads();

    const int tq = tid >> 4;
    const int tk = tid & 15;

    float dot[2][2] = {{0.f, 0.f}, {0.f, 0.f}};
    for (int d = 0; d < 128; d++) {
        float2 qv = *(const float2*)&qs[d][tq * 2];
        float2 pv = *(const float2*)&ps[d][tk * 2];
        dot[0][0] = fmaf(qv.x, pv.x, dot[0][0]);
        dot[0][1] = fmaf(qv.x, pv.y, dot[0][1]);
        dot[1][0] = fmaf(qv.y, pv.x, dot[1][0]);
        dot[1][1] = fmaf(qv.y, pv.y, dot[1][1]);
    }

    #pragma unroll
    for (int i = 0; i < 2; i++) {
        float m = -3.4e38f;
        bool any = false;
        #pragma unroll
        for (int j = 0; j < 2; j++) {
            int kk = k0 + tk * 2 + j;
            if (kk < kb) { m = fmaxf(m, dot[i][j]); any = true; }
        }
        if (any)
            atomicMax(&g_qmax[b * LQ_ + q0 + tq * 2 + i], flipf(m));
    }
}

// ======================= final reduction =======================
__global__ void final_kernel(const int* __restrict__ q_mask,
                             float* __restrict__ out) {
    const int b = blockIdx.x;
    const int t = threadIdx.x;
    float v = unflipf(g_qmax[b * LQ_ + t]) * (float)q_mask[b * LQ_ + t];
    for (int o = 16; o; o >>= 1) v += __shfl_down_sync(0xffffffffu, v, o);
    __shared__ float sm[2];
    if ((t & 31) == 0) sm[t >> 5] = v;
    __syncthreads();
    if (t == 0) out[b] = sm[0] + sm[1];
}

// ======================= launch =======================
extern "C" void kernel_launch(void* const* d_in, const int* in_sizes, int n_in,
                              void* d_out, int out_size) {
    const float* q_hidden = (const float*)d_in[0];
    const float* d_hidden = (const float*)d_in[1];
    const float* Wm       = (const float*)d_in[2];
    const float* bias     = (const float*)d_in[3];
    const int*   q_mask   = (const int*)  d_in[4];
    const int*   d_mask   = (const int*)  d_in[5];
    const int*   labels   = (const int*)  d_in[6];
    const int*   pf       = (const int*)  d_in[7];
    float*       out      = (float*)d_out;

    cudaFuncSetAttribute(encode_kernel,
                         cudaFuncAttributeMaxDynamicSharedMemorySize, SMEM_DYN);

    wsplit_kernel<<<512, 256>>>(Wm);
    init_kernel<<<2048, 256>>>();
    kb_kernel<<<B_, 256>>>(d_mask, pf);
    encode_kernel<<<QBLK + DBLK, 256, SMEM_DYN>>>(q_hidden, d_hidden, bias,
                                                  q_mask, d_mask, labels);
    cnt_kernel<<<MD / 256, 256>>>(d_mask, labels);
    finalize_kernel<<<B_ * KPAD, 128>>>();
    dim3 sg(KPAD / 32, LQ_ / 32, B_);
    score_kernel<<<sg, 256>>>();
    final_kernel<<<B_, 64>>>(q_mask, out);
}

// round 7
// speedup vs baseline: 1.8770x; 1.1980x over previous
#include <cuda_runtime.h>
#include <cuda_bf16.h>
#include <math.h>
#include <cstdint>

// Problem constants
#define B_    16
#define LQ_   64
#define LD_   2048
#define H_    1024
#define DIM_  128
#define KPAD  2112
#define MQ    (B_ * LQ_)      // 1024
#define MD    (B_ * LD_)      // 32768
#define QBLK  (MQ / 64)       // 16
#define DBLK  (MD / 64)       // 512

// -------- scratch --------
__device__ float          g_q_repr[MQ * DIM_];
__device__ float          g_pool  [B_ * KPAD * DIM_];
__device__ int            g_kb    [B_];
__device__ unsigned int   g_qmax  [B_ * LQ_];
__device__ __nv_bfloat16  g_Wt_hi [DIM_ * H_];   // [n][k]
__device__ __nv_bfloat16  g_Wt_lo [DIM_ * H_];   // [n][k]

__device__ __forceinline__ unsigned int flipf(float f) {
    unsigned int u = __float_as_uint(f);
    return (u & 0x80000000u) ? ~u : (u | 0x80000000u);
}
__device__ __forceinline__ float unflipf(unsigned int u) {
    return (u & 0x80000000u) ? __uint_as_float(u ^ 0x80000000u)
                             : __uint_as_float(~u);
}
__device__ __forceinline__ uint32_t smem_to_u32(const void* p) {
    uint32_t a;
    asm("{ .reg .u64 t; cvta.to.shared.u64 t, %1; cvt.u32.u64 %0, t; }"
        : "=r"(a) : "l"(p));
    return a;
}
#define CP_ASYNC16(dst, src) \
    asm volatile("cp.async.cg.shared.global [%0], [%1], 16;" \
                 :: "r"((uint32_t)(dst)), "l"(src) : "memory")
#define CP_COMMIT() asm volatile("cp.async.commit_group;" ::: "memory")
#define CP_WAIT0()  asm volatile("cp.async.wait_group 0;" ::: "memory")
#define STS64V(addr, a, b) \
    asm volatile("st.shared.v2.b32 [%0], {%1,%2};" \
                 :: "r"((uint32_t)(addr)), "r"(a), "r"(b) : "memory")
#define LDSM_X4(r, addr) \
    asm volatile("ldmatrix.sync.aligned.m8n8.x4.shared.b16 {%0,%1,%2,%3}, [%4];" \
                 : "=r"((r)[0]), "=r"((r)[1]), "=r"((r)[2]), "=r"((r)[3]) \
                 : "r"((uint32_t)(addr)))
#define MMA16816(cc, a, b0, b1) \
    asm volatile( \
        "mma.sync.aligned.m16n8k16.row.col.f32.bf16.bf16.f32 " \
        "{%0,%1,%2,%3}, {%4,%5,%6,%7}, {%8,%9}, {%0,%1,%2,%3};" \
        : "+f"((cc)[0]), "+f"((cc)[1]), "+f"((cc)[2]), "+f"((cc)[3]) \
        : "r"((a)[0]), "r"((a)[1]), "r"((a)[2]), "r"((a)[3]), \
          "r"(b0), "r"(b1))

// ======================= prep: wsplit + init + kb (fused) =======================
__global__ void prep_kernel(const float* __restrict__ Wm,
                            const int* __restrict__ d_mask,
                            const int* __restrict__ pf) {
    const int blk = blockIdx.x;
    const int tid = threadIdx.x;
    if (blk < 2048) {
        const int n = B_ * KPAD * DIM_;
        for (int i = blk * 256 + tid; i < n; i += 2048 * 256) {
            g_pool[i] = 0.0f;
            if (i < B_ * LQ_) g_qmax[i] = flipf(-1e4f);
        }
        if (blk < 512) {
            int i = blk * 256 + tid;            // 0..131071
            int k = i >> 7, nn = i & 127;
            float w = Wm[i];
            __nv_bfloat16 hi = __float2bfloat16(w);
            g_Wt_hi[nn * H_ + k] = hi;
            g_Wt_lo[nn * H_ + k] = __float2bfloat16(w - __bfloat162float(hi));
        }
    } else {
        const int b = blk - 2048;               // 0..15
        int s = 0;
        for (int i = tid; i < LD_; i += 256)
            s += (d_mask[b * LD_ + i] > 0) ? 1 : 0;
        __shared__ int sm[8];
        for (int o = 16; o; o >>= 1) s += __shfl_down_sync(0xffffffffu, s, o);
        if ((tid & 31) == 0) sm[tid >> 5] = s;
        __syncthreads();
        if (tid == 0) {
            int t = 0;
            #pragma unroll
            for (int w = 0; w < 8; w++) t += sm[w];
            if (t < 2) t = 2;
            int p = pf[0]; if (p < 1) p = 1;
            int k = t / p + 1;
            if (k > KPAD) k = KPAD;
            g_kb[b] = k;
        }
    }
}

// ======================= fused encode (mma.sync + ldmatrix, 2 CTA/SM) ==========
// grid = 528: [0,16) -> q tiles, [16,528) -> d tiles. BM=64, BN=128, BK=16.
// 8 warps, warp tile 32x32 (mt=2, nt=4), 3-split bf16, double-buffered smem.
#define ASTR     24                    // bf16 elems per smem row (48 B)
#define A_ARR_B  (64 * ASTR * 2)       // 3072
#define W_ARR_B  (128 * ASTR * 2)      // 6144
#define STAGE_B  (2 * A_ARR_B + 2 * W_ARR_B)   // 18432
#define SMEM_DYN (2 * STAGE_B)                 // 36864

__global__ __launch_bounds__(256, 2) void encode_kernel(
        const float* __restrict__ q_hidden,
        const float* __restrict__ d_hidden,
        const float* __restrict__ bias,
        const int*   __restrict__ q_mask,
        const int*   __restrict__ d_mask,
        const int*   __restrict__ labels)
{
    extern __shared__ char smem[];
    __shared__ float red[64][4];
    __shared__ float scales[64];
    __shared__ int   labsm[64];

    const uint32_t sb32 = smem_to_u32(smem);
    const int tid  = threadIdx.x;
    const int warp = tid >> 5;
    const int lane = tid & 31;
    const int g    = lane >> 2;
    const int tg   = lane & 3;
    const int wm   = warp >> 2;     // 0..1
    const int wn   = warp & 3;      // 0..3

    const bool is_q = (blockIdx.x < QBLK);
    const float* A    = is_q ? q_hidden : d_hidden;
    const int*   mask = is_q ? q_mask   : d_mask;
    const int    bm   = is_q ? (int)blockIdx.x * 64 : ((int)blockIdx.x - QBLK) * 64;

    float c[2][4][4];
    #pragma unroll
    for (int mt = 0; mt < 2; mt++)
        #pragma unroll
        for (int nt = 0; nt < 4; nt++)
            #pragma unroll
            for (int r = 0; r < 4; r++) c[mt][nt][r] = 0.0f;

    // A-load mapping: 4 threads/row, 4 elems each
    const int arow = tid >> 2;
    const int aq   = (tid & 3) * 4;
    const float* aptr = A + (size_t)(bm + arow) * H_ + aq;
    const uint32_t a_sts = (uint32_t)(arow * 48 + aq * 2);
    // W-load mapping: 2 threads/row, 8 elems each (cp.async 16B)
    const int wrow = tid >> 1;
    const int wq   = (tid & 1) * 8;
    const __nv_bfloat16* whp = g_Wt_hi + (size_t)wrow * H_ + wq;
    const __nv_bfloat16* wlp = g_Wt_lo + (size_t)wrow * H_ + wq;
    const uint32_t w_sts = (uint32_t)(wrow * 48 + wq * 2);

    // ldmatrix per-lane offsets (bytes within a tile array)
    const uint32_t a_ld = (uint32_t)((wm * 32 + (lane & 15)) * 48 + (lane >> 4) * 16);
    const uint32_t b_ld = (uint32_t)((wn * 32 + (lane & 7) + ((lane >> 4) << 3)) * 48
                                     + ((lane >> 3) & 1) * 16);

    // stage bases
    const uint32_t st0 = sb32;
    const uint32_t st1 = sb32 + STAGE_B;

    auto put_a = [&](uint32_t stage, float4 a) {
        __nv_bfloat16 h0 = __float2bfloat16(a.x);
        __nv_bfloat16 h1 = __float2bfloat16(a.y);
        __nv_bfloat16 h2 = __float2bfloat16(a.z);
        __nv_bfloat16 h3 = __float2bfloat16(a.w);
        __nv_bfloat162 hp0(h0, h1), hp1(h2, h3);
        __nv_bfloat162 lp0(__float2bfloat16(a.x - __bfloat162float(h0)),
                           __float2bfloat16(a.y - __bfloat162float(h1)));
        __nv_bfloat162 lp1(__float2bfloat16(a.z - __bfloat162float(h2)),
                           __float2bfloat16(a.w - __bfloat162float(h3)));
        STS64V(stage + a_sts, *(uint32_t*)&hp0, *(uint32_t*)&hp1);
        STS64V(stage + A_ARR_B + a_sts, *(uint32_t*)&lp0, *(uint32_t*)&lp1);
    };

    // ---- preload stage 0 ----
    {
        CP_ASYNC16(st0 + 2 * A_ARR_B + w_sts, whp);
        CP_ASYNC16(st0 + 2 * A_ARR_B + W_ARR_B + w_sts, wlp);
        CP_COMMIT();
        float4 a0 = *(const float4*)aptr;
        put_a(st0, a0);
        CP_WAIT0();
    }
    __syncthreads();

    const int NIT = H_ / 16;   // 64
    for (int it = 0; it < NIT; it++) {
        const uint32_t cb = (it & 1) ? st1 : st0;
        const uint32_t nb = (it & 1) ? st0 : st1;
        float4 na;
        if (it + 1 < NIT) {
            const int ko = (it + 1) * 16;
            CP_ASYNC16(nb + 2 * A_ARR_B + w_sts, whp + ko);
            CP_ASYNC16(nb + 2 * A_ARR_B + W_ARR_B + w_sts, wlp + ko);
            CP_COMMIT();
            na = *(const float4*)(aptr + ko);
        }

        // ---- fragments via ldmatrix ----
        uint32_t afh[2][4], afl[2][4], bh[8], bl[8];
        LDSM_X4(afh[0], cb + a_ld);
        LDSM_X4(afh[1], cb + a_ld + 768);
        LDSM_X4(afl[0], cb + A_ARR_B + a_ld);
        LDSM_X4(afl[1], cb + A_ARR_B + a_ld + 768);
        LDSM_X4(&bh[0], cb + 2 * A_ARR_B + b_ld);
        LDSM_X4(&bh[4], cb + 2 * A_ARR_B + b_ld + 768);
        LDSM_X4(&bl[0], cb + 2 * A_ARR_B + W_ARR_B + b_ld);
        LDSM_X4(&bl[4], cb + 2 * A_ARR_B + W_ARR_B + b_ld + 768);

        #pragma unroll
        for (int mt = 0; mt < 2; mt++)
            #pragma unroll
            for (int nt = 0; nt < 4; nt++) {
                MMA16816(c[mt][nt], afh[mt], bh[nt * 2], bh[nt * 2 + 1]);
                MMA16816(c[mt][nt], afh[mt], bl[nt * 2], bl[nt * 2 + 1]);
                MMA16816(c[mt][nt], afl[mt], bh[nt * 2], bh[nt * 2 + 1]);
            }

        if (it + 1 < NIT) {
            put_a(nb, na);
            CP_WAIT0();
        }
        __syncthreads();
    }

    // ---- bias ----
    #pragma unroll
    for (int nt = 0; nt < 4; nt++) {
        int bcol = wn * 32 + nt * 8 + 2 * tg;
        float2 bb = *(const float2*)&bias[bcol];
        #pragma unroll
        for (int mt = 0; mt < 2; mt++) {
            c[mt][nt][0] += bb.x; c[mt][nt][1] += bb.y;
            c[mt][nt][2] += bb.x; c[mt][nt][3] += bb.y;
        }
    }

    // ---- row sum-of-squares ----
    #pragma unroll
    for (int mt = 0; mt < 2; mt++) {
        float slo = 0.0f, shi = 0.0f;
        #pragma unroll
        for (int nt = 0; nt < 4; nt++) {
            slo = fmaf(c[mt][nt][0], c[mt][nt][0], slo);
            slo = fmaf(c[mt][nt][1], c[mt][nt][1], slo);
            shi = fmaf(c[mt][nt][2], c[mt][nt][2], shi);
            shi = fmaf(c[mt][nt][3], c[mt][nt][3], shi);
        }
        slo += __shfl_xor_sync(0xffffffffu, slo, 1);
        slo += __shfl_xor_sync(0xffffffffu, slo, 2);
        shi += __shfl_xor_sync(0xffffffffu, shi, 1);
        shi += __shfl_xor_sync(0xffffffffu, shi, 2);
        if (tg == 0) {
            red[wm * 32 + mt * 16 + g][wn]     = slo;
            red[wm * 32 + mt * 16 + g + 8][wn] = shi;
        }
    }
    __syncthreads();

    if (tid < 64) {
        float tot = red[tid][0] + red[tid][1] + red[tid][2] + red[tid][3];
        float scale = 1.0f / fmaxf(sqrtf(tot), 1e-12f);
        scales[tid] = scale * (float)mask[bm + tid];
        if (!is_q) {
            int r = bm + tid;
            int b = r >> 11;
            labsm[tid] = (b * KPAD + labels[r] % g_kb[b]) * DIM_;
        }
    }
    __syncthreads();

    if (is_q) {
        #pragma unroll
        for (int mt = 0; mt < 2; mt++) {
            int rl = wm * 32 + mt * 16 + g;
            float sl = scales[rl], sh = scales[rl + 8];
            #pragma unroll
            for (int nt = 0; nt < 4; nt++) {
                int col = wn * 32 + nt * 8 + 2 * tg;
                float2 v0 = make_float2(c[mt][nt][0] * sl, c[mt][nt][1] * sl);
                float2 v1 = make_float2(c[mt][nt][2] * sh, c[mt][nt][3] * sh);
                *(float2*)&g_q_repr[(size_t)(bm + rl) * DIM_ + col]     = v0;
                *(float2*)&g_q_repr[(size_t)(bm + rl + 8) * DIM_ + col] = v1;
            }
        }
    } else {
        #pragma unroll
        for (int mt = 0; mt < 2; mt++) {
            int rl = wm * 32 + mt * 16 + g;
            float sl = scales[rl], sh = scales[rl + 8];
            int dl = labsm[rl], dh = labsm[rl + 8];
            #pragma unroll
            for (int nt = 0; nt < 4; nt++) {
                int col = wn * 32 + nt * 8 + 2 * tg;
                atomicAdd(&g_pool[dl + col],     c[mt][nt][0] * sl);
                atomicAdd(&g_pool[dl + col + 1], c[mt][nt][1] * sl);
                atomicAdd(&g_pool[dh + col],     c[mt][nt][2] * sh);
                atomicAdd(&g_pool[dh + col + 1], c[mt][nt][3] * sh);
            }
        }
    }
}

// ======================= pool finalize: normalize sums ======================
// means/||means|| == sums/||sums|| (count division cancels), so no counts.
__global__ void finalize_kernel() {
    const int idx = blockIdx.x;
    const int b   = idx / KPAD;
    const int kk  = idx % KPAD;
    if (kk >= g_kb[b]) return;
    const int t = threadIdx.x;
    float v = g_pool[((size_t)idx << 7) + t];
    float s = v * v;
    for (int o = 16; o; o >>= 1) s += __shfl_down_sync(0xffffffffu, s, o);
    __shared__ float sm[4];
    __shared__ float tot;
    if ((t & 31) == 0) sm[t >> 5] = s;
    __syncthreads();
    if (t == 0) tot = sm[0] + sm[1] + sm[2] + sm[3];
    __syncthreads();
    float scale = 1.0f / fmaxf(sqrtf(tot), 1e-12f);
    g_pool[((size_t)idx << 7) + t] = v * scale;
}

// ======================= sim + running max =======================
__global__ __launch_bounds__(256) void score_kernel() {
    const int b  = blockIdx.z;
    const int kb = g_kb[b];
    const int k0 = blockIdx.x * 32;
    if (k0 >= kb) return;
    const int q0 = blockIdx.y * 32;

    __shared__ float qs[128][36];
    __shared__ float ps[128][36];

    const int tid = threadIdx.x;
    for (int lin = tid; lin < 32 * 128; lin += 256) {
        int r = lin >> 7, d = lin & 127;
        qs[d][r] = g_q_repr[((size_t)(b * LQ_ + q0 + r) << 7) + d];
        ps[d][r] = g_pool  [((size_t)(b * KPAD + k0 + r) << 7) + d];
    }
    __syncthreads();

    const int tq = tid >> 4;
    const int tk = tid & 15;

    float dot[2][2] = {{0.f, 0.f}, {0.f, 0.f}};
    for (int d = 0; d < 128; d++) {
        float2 qv = *(const float2*)&qs[d][tq * 2];
        float2 pv = *(const float2*)&ps[d][tk * 2];
        dot[0][0] = fmaf(qv.x, pv.x, dot[0][0]);
        dot[0][1] = fmaf(qv.x, pv.y, dot[0][1]);
        dot[1][0] = fmaf(qv.y, pv.x, dot[1][0]);
        dot[1][1] = fmaf(qv.y, pv.y, dot[1][1]);
    }

    #pragma unroll
    for (int i = 0; i < 2; i++) {
        float m = -3.4e38f;
        bool any = false;
        #pragma unroll
        for (int j = 0; j < 2; j++) {
            int kk = k0 + tk * 2 + j;
            if (kk < kb) { m = fmaxf(m, dot[i][j]); any = true; }
        }
        if (any)
            atomicMax(&g_qmax[b * LQ_ + q0 + tq * 2 + i], flipf(m));
    }
}

// ======================= final reduction =======================
__global__ void final_kernel(const int* __restrict__ q_mask,
                             float* __restrict__ out) {
    const int b = blockIdx.x;
    const int t = threadIdx.x;
    float v = unflipf(g_qmax[b * LQ_ + t]) * (float)q_mask[b * LQ_ + t];
    for (int o = 16; o; o >>= 1) v += __shfl_down_sync(0xffffffffu, v, o);
    __shared__ float sm[2];
    if ((t & 31) == 0) sm[t >> 5] = v;
    __syncthreads();
    if (t == 0) out[b] = sm[0] + sm[1];
}

// ======================= launch =======================
extern "C" void kernel_launch(void* const* d_in, const int* in_sizes, int n_in,
                              void* d_out, int out_size) {
    const float* q_hidden = (const float*)d_in[0];
    const float* d_hidden = (const float*)d_in[1];
    const float* Wm       = (const float*)d_in[2];
    const float* bias     = (const float*)d_in[3];
    const int*   q_mask   = (const int*)  d_in[4];
    const int*   d_mask   = (const int*)  d_in[5];
    const int*   labels   = (const int*)  d_in[6];
    const int*   pf       = (const int*)  d_in[7];
    float*       out      = (float*)d_out;

    cudaFuncSetAttribute(encode_kernel,
                         cudaFuncAttributeMaxDynamicSharedMemorySize, SMEM_DYN);

    prep_kernel<<<2064, 256>>>(Wm, d_mask, pf);
    encode_kernel<<<QBLK + DBLK, 256, SMEM_DYN>>>(q_hidden, d_hidden, bias,
                                                  q_mask, d_mask, labels);
    finalize_kernel<<<B_ * KPAD, 128>>>();
    dim3 sg(KPAD / 32, LQ_ / 32, B_);
    score_kernel<<<sg, 256>>>();
    final_kernel<<<B_, 64>>>(q_mask, out);
}

// round 8
// speedup vs baseline: 3.4656x; 1.8464x over previous
#include <cuda_runtime.h>
#include <cuda_bf16.h>
#include <math.h>
#include <cstdint>

// Problem constants
#define B_    16
#define LQ_   64
#define LD_   2048
#define H_    1024
#define DIM_  128
#define KPAD  2112
#define MQ    (B_ * LQ_)      // 1024
#define MD    (B_ * LD_)      // 32768
#define QBLK  (MQ / 64)       // 16
#define DBLK  (MD / 64)       // 512

// -------- scratch --------
__device__ float          g_q_repr[MQ * DIM_];
__device__ float          g_pool  [B_ * KPAD * DIM_];   // segment sums (raw)
__device__ int            g_kb    [B_];
__device__ unsigned int   g_qmax  [B_ * LQ_];
__device__ __nv_bfloat16  g_Wt_hi [DIM_ * H_];   // [n][k]
__device__ __nv_bfloat16  g_Wt_lo [DIM_ * H_];   // [n][k]

__device__ __forceinline__ unsigned int flipf(float f) {
    unsigned int u = __float_as_uint(f);
    return (u & 0x80000000u) ? ~u : (u | 0x80000000u);
}
__device__ __forceinline__ float unflipf(unsigned int u) {
    return (u & 0x80000000u) ? __uint_as_float(u ^ 0x80000000u)
                             : __uint_as_float(~u);
}
__device__ __forceinline__ uint32_t smem_to_u32(const void* p) {
    uint32_t a;
    asm("{ .reg .u64 t; cvta.to.shared.u64 t, %1; cvt.u32.u64 %0, t; }"
        : "=r"(a) : "l"(p));
    return a;
}
#define CP_ASYNC16(dst, src) \
    asm volatile("cp.async.cg.shared.global [%0], [%1], 16;" \
                 :: "r"((uint32_t)(dst)), "l"(src) : "memory")
#define CP_COMMIT() asm volatile("cp.async.commit_group;" ::: "memory")
#define CP_WAIT0()  asm volatile("cp.async.wait_group 0;" ::: "memory")
#define STS128U(addr, a, b, c, d) \
    asm volatile("st.shared.v4.b32 [%0], {%1,%2,%3,%4};" \
                 :: "r"((uint32_t)(addr)), "r"(a), "r"(b), "r"(c), "r"(d) : "memory")
#define LDSM_X4(r, addr) \
    asm volatile("ldmatrix.sync.aligned.m8n8.x4.shared.b16 {%0,%1,%2,%3}, [%4];" \
                 : "=r"((r)[0]), "=r"((r)[1]), "=r"((r)[2]), "=r"((r)[3]) \
                 : "r"((uint32_t)(addr)))
#define MMA16816(cc, a, b0, b1) \
    asm volatile( \
        "mma.sync.aligned.m16n8k16.row.col.f32.bf16.bf16.f32 " \
        "{%0,%1,%2,%3}, {%4,%5,%6,%7}, {%8,%9}, {%0,%1,%2,%3};" \
        : "+f"((cc)[0]), "+f"((cc)[1]), "+f"((cc)[2]), "+f"((cc)[3]) \
        : "r"((a)[0]), "r"((a)[1]), "r"((a)[2]), "r"((a)[3]), \
          "r"(b0), "r"(b1))

// ======================= prep: wsplit + init + kb (fused) =======================
__global__ void prep_kernel(const float* __restrict__ Wm,
                            const int* __restrict__ d_mask,
                            const int* __restrict__ pf) {
    const int blk = blockIdx.x;
    const int tid = threadIdx.x;
    if (blk < 2048) {
        const int n = B_ * KPAD * DIM_;
        for (int i = blk * 256 + tid; i < n; i += 2048 * 256) {
            g_pool[i] = 0.0f;
            if (i < B_ * LQ_) g_qmax[i] = flipf(-1e4f);
        }
        if (blk < 512) {
            int i = blk * 256 + tid;            // 0..131071
            int k = i >> 7, nn = i & 127;
            float w = Wm[i];
            __nv_bfloat16 hi = __float2bfloat16(w);
            g_Wt_hi[nn * H_ + k] = hi;
            g_Wt_lo[nn * H_ + k] = __float2bfloat16(w - __bfloat162float(hi));
        }
    } else {
        const int b = blk - 2048;               // 0..15
        int s = 0;
        for (int i = tid; i < LD_; i += 256)
            s += (d_mask[b * LD_ + i] > 0) ? 1 : 0;
        __shared__ int sm[8];
        for (int o = 16; o; o >>= 1) s += __shfl_down_sync(0xffffffffu, s, o);
        if ((tid & 31) == 0) sm[tid >> 5] = s;
        __syncthreads();
        if (tid == 0) {
            int t = 0;
            #pragma unroll
            for (int w = 0; w < 8; w++) t += sm[w];
            if (t < 2) t = 2;
            int p = pf[0]; if (p < 1) p = 1;
            int k = t / p + 1;
            if (k > KPAD) k = KPAD;
            g_kb[b] = k;
        }
    }
}

// ======================= fused encode (mma.sync + ldmatrix, BK=32) ==========
// grid = 528: [0,16) -> q tiles, [16,528) -> d tiles. BM=64, BN=128, BK=32.
// 8 warps, warp tile 32x32 (mt=2, nt=4), 3-split bf16, double-buffered smem.
#define ROWB     80                    // bytes per smem row (32 bf16 + pad)
#define A_ARR_B  (64 * ROWB)           // 5120
#define W_ARR_B  (128 * ROWB)          // 10240
#define STAGE_B  (2 * A_ARR_B + 2 * W_ARR_B)   // 30720
#define SMEM_DYN (2 * STAGE_B)                 // 61440

__global__ __launch_bounds__(256, 2) void encode_kernel(
        const float* __restrict__ q_hidden,
        const float* __restrict__ d_hidden,
        const float* __restrict__ bias,
        const int*   __restrict__ q_mask,
        const int*   __restrict__ d_mask,
        const int*   __restrict__ labels)
{
    extern __shared__ char smem[];
    __shared__ float red[64][4];
    __shared__ float scales[64];
    __shared__ int   labsm[64];

    const uint32_t sb32 = smem_to_u32(smem);
    const int tid  = threadIdx.x;
    const int warp = tid >> 5;
    const int lane = tid & 31;
    const int g    = lane >> 2;
    const int tg   = lane & 3;
    const int wm   = warp >> 2;     // 0..1
    const int wn   = warp & 3;      // 0..3

    const bool is_q = (blockIdx.x < QBLK);
    const float* A    = is_q ? q_hidden : d_hidden;
    const int*   mask = is_q ? q_mask   : d_mask;
    const int    bm   = is_q ? (int)blockIdx.x * 64 : ((int)blockIdx.x - QBLK) * 64;

    float c[2][4][4];
    #pragma unroll
    for (int mt = 0; mt < 2; mt++)
        #pragma unroll
        for (int nt = 0; nt < 4; nt++)
            #pragma unroll
            for (int r = 0; r < 4; r++) c[mt][nt][r] = 0.0f;

    // A-load: 4 threads/row, 8 fp32 each
    const int arow = tid >> 2;
    const int aq   = (tid & 3) * 8;
    const float* aptr = A + (size_t)(bm + arow) * H_ + aq;
    const uint32_t a_sts = (uint32_t)(arow * ROWB + aq * 2);
    // W-load: 2 cp.async chunks per thread per array
    const int wr0 = tid >> 2;                 // chunk c = tid: row tid>>2
    const int wq0 = (tid & 3) * 8;
    const int wr1 = (tid + 256) >> 2;
    const int wq1 = ((tid + 256) & 3) * 8;
    const __nv_bfloat16* whp0 = g_Wt_hi + (size_t)wr0 * H_ + wq0;
    const __nv_bfloat16* whp1 = g_Wt_hi + (size_t)wr1 * H_ + wq1;
    const __nv_bfloat16* wlp0 = g_Wt_lo + (size_t)wr0 * H_ + wq0;
    const __nv_bfloat16* wlp1 = g_Wt_lo + (size_t)wr1 * H_ + wq1;
    const uint32_t w_sts0 = (uint32_t)(wr0 * ROWB + wq0 * 2);
    const uint32_t w_sts1 = (uint32_t)(wr1 * ROWB + wq1 * 2);

    // ldmatrix per-lane offsets (bytes within a tile array)
    const uint32_t a_ld = (uint32_t)((wm * 32 + (lane & 15)) * ROWB + (lane >> 4) * 16);
    const uint32_t b_ld = (uint32_t)((wn * 32 + (lane & 7) + ((lane >> 4) << 3)) * ROWB
                                     + ((lane >> 3) & 1) * 16);

    const uint32_t st0 = sb32;
    const uint32_t st1 = sb32 + STAGE_B;

    auto put_a = [&](uint32_t stage, float4 a0, float4 a1) {
        float av[8] = {a0.x, a0.y, a0.z, a0.w, a1.x, a1.y, a1.z, a1.w};
        uint32_t hw[4], lw[4];
        #pragma unroll
        for (int q = 0; q < 4; q++) {
            __nv_bfloat16 h0 = __float2bfloat16(av[2 * q]);
            __nv_bfloat16 h1 = __float2bfloat16(av[2 * q + 1]);
            __nv_bfloat162 hp(h0, h1);
            __nv_bfloat162 lp(__float2bfloat16(av[2 * q]     - __bfloat162float(h0)),
                              __float2bfloat16(av[2 * q + 1] - __bfloat162float(h1)));
            hw[q] = *(uint32_t*)&hp;
            lw[q] = *(uint32_t*)&lp;
        }
        STS128U(stage + a_sts, hw[0], hw[1], hw[2], hw[3]);
        STS128U(stage + A_ARR_B + a_sts, lw[0], lw[1], lw[2], lw[3]);
    };
    auto load_w = [&](uint32_t stage, int k0) {
        const uint32_t wh = stage + 2 * A_ARR_B;
        const uint32_t wl = wh + W_ARR_B;
        CP_ASYNC16(wh + w_sts0, whp0 + k0);
        CP_ASYNC16(wh + w_sts1, whp1 + k0);
        CP_ASYNC16(wl + w_sts0, wlp0 + k0);
        CP_ASYNC16(wl + w_sts1, wlp1 + k0);
    };

    // ---- preload stage 0 ----
    {
        load_w(st0, 0);
        CP_COMMIT();
        float4 a0 = *(const float4*)aptr;
        float4 a1 = *(const float4*)(aptr + 4);
        put_a(st0, a0, a1);
        CP_WAIT0();
    }
    __syncthreads();

    const int NIT = H_ / 32;   // 32
    for (int it = 0; it < NIT; it++) {
        const uint32_t cb = (it & 1) ? st1 : st0;
        const uint32_t nb = (it & 1) ? st0 : st1;
        float4 na0, na1;
        if (it + 1 < NIT) {
            const int ko = (it + 1) * 32;
            load_w(nb, ko);
            CP_COMMIT();
            na0 = *(const float4*)(aptr + ko);
            na1 = *(const float4*)(aptr + ko + 4);
        }

        #pragma unroll
        for (int ksub = 0; ksub < 2; ksub++) {
            const uint32_t ko = ksub * 32;     // byte offset within row
            uint32_t afh[2][4], afl[2][4], bh[8], bl[8];
            LDSM_X4(afh[0], cb + a_ld + ko);
            LDSM_X4(afh[1], cb + a_ld + ko + 16 * ROWB);
            LDSM_X4(afl[0], cb + A_ARR_B + a_ld + ko);
            LDSM_X4(afl[1], cb + A_ARR_B + a_ld + ko + 16 * ROWB);
            LDSM_X4(&bh[0], cb + 2 * A_ARR_B + b_ld + ko);
            LDSM_X4(&bh[4], cb + 2 * A_ARR_B + b_ld + ko + 16 * ROWB);
            LDSM_X4(&bl[0], cb + 2 * A_ARR_B + W_ARR_B + b_ld + ko);
            LDSM_X4(&bl[4], cb + 2 * A_ARR_B + W_ARR_B + b_ld + ko + 16 * ROWB);
            #pragma unroll
            for (int mt = 0; mt < 2; mt++)
                #pragma unroll
                for (int nt = 0; nt < 4; nt++) {
                    MMA16816(c[mt][nt], afh[mt], bh[nt * 2], bh[nt * 2 + 1]);
                    MMA16816(c[mt][nt], afh[mt], bl[nt * 2], bl[nt * 2 + 1]);
                    MMA16816(c[mt][nt], afl[mt], bh[nt * 2], bh[nt * 2 + 1]);
                }
        }

        if (it + 1 < NIT) {
            put_a(nb, na0, na1);
            CP_WAIT0();
        }
        __syncthreads();
    }

    // ---- bias ----
    #pragma unroll
    for (int nt = 0; nt < 4; nt++) {
        int bcol = wn * 32 + nt * 8 + 2 * tg;
        float2 bb = *(const float2*)&bias[bcol];
        #pragma unroll
        for (int mt = 0; mt < 2; mt++) {
            c[mt][nt][0] += bb.x; c[mt][nt][1] += bb.y;
            c[mt][nt][2] += bb.x; c[mt][nt][3] += bb.y;
        }
    }

    // ---- row sum-of-squares ----
    #pragma unroll
    for (int mt = 0; mt < 2; mt++) {
        float slo = 0.0f, shi = 0.0f;
        #pragma unroll
        for (int nt = 0; nt < 4; nt++) {
            slo = fmaf(c[mt][nt][0], c[mt][nt][0], slo);
            slo = fmaf(c[mt][nt][1], c[mt][nt][1], slo);
            shi = fmaf(c[mt][nt][2], c[mt][nt][2], shi);
            shi = fmaf(c[mt][nt][3], c[mt][nt][3], shi);
        }
        slo += __shfl_xor_sync(0xffffffffu, slo, 1);
        slo += __shfl_xor_sync(0xffffffffu, slo, 2);
        shi += __shfl_xor_sync(0xffffffffu, shi, 1);
        shi += __shfl_xor_sync(0xffffffffu, shi, 2);
        if (tg == 0) {
            red[wm * 32 + mt * 16 + g][wn]     = slo;
            red[wm * 32 + mt * 16 + g + 8][wn] = shi;
        }
    }
    __syncthreads();

    if (tid < 64) {
        float tot = red[tid][0] + red[tid][1] + red[tid][2] + red[tid][3];
        float scale = 1.0f / fmaxf(sqrtf(tot), 1e-12f);
        scales[tid] = scale * (float)mask[bm + tid];
        if (!is_q) {
            int r = bm + tid;
            int b = r >> 11;
            labsm[tid] = (b * KPAD + labels[r] % g_kb[b]) * DIM_;
        }
    }
    __syncthreads();

    if (is_q) {
        #pragma unroll
        for (int mt = 0; mt < 2; mt++) {
            int rl = wm * 32 + mt * 16 + g;
            float sl = scales[rl], sh = scales[rl + 8];
            #pragma unroll
            for (int nt = 0; nt < 4; nt++) {
                int col = wn * 32 + nt * 8 + 2 * tg;
                float2 v0 = make_float2(c[mt][nt][0] * sl, c[mt][nt][1] * sl);
                float2 v1 = make_float2(c[mt][nt][2] * sh, c[mt][nt][3] * sh);
                *(float2*)&g_q_repr[(size_t)(bm + rl) * DIM_ + col]     = v0;
                *(float2*)&g_q_repr[(size_t)(bm + rl + 8) * DIM_ + col] = v1;
            }
        }
    } else {
        #pragma unroll
        for (int mt = 0; mt < 2; mt++) {
            int rl = wm * 32 + mt * 16 + g;
            float sl = scales[rl], sh = scales[rl + 8];
            int dl = labsm[rl], dh = labsm[rl + 8];
            #pragma unroll
            for (int nt = 0; nt < 4; nt++) {
                int col = wn * 32 + nt * 8 + 2 * tg;
                atomicAdd(&g_pool[dl + col],     c[mt][nt][0] * sl);
                atomicAdd(&g_pool[dl + col + 1], c[mt][nt][1] * sl);
                atomicAdd(&g_pool[dh + col],     c[mt][nt][2] * sh);
                atomicAdd(&g_pool[dh + col + 1], c[mt][nt][3] * sh);
            }
        }
    }
}

// ======================= score: normalize pool tile + sim + max =======================
// grid (KPAD/64, B_). Block: all 64 q x 64 clusters, 4x4 micro-tile.
// Cluster normalization fused here (sums/||sums|| == means/||means||).
#define SC_STR   72                              // floats per smem row
#define SC_ARR_B (128 * SC_STR * 4)              // 36864
#define SC_SMEM  (2 * SC_ARR_B)                  // 73728

__global__ __launch_bounds__(256) void score_kernel() {
    const int b  = blockIdx.y;
    const int kb = g_kb[b];
    const int k0 = blockIdx.x * 64;
    if (k0 >= kb) return;

    extern __shared__ float ss[];
    float (*qs)[SC_STR] = (float(*)[SC_STR])ss;             // [d][q]
    float (*ps)[SC_STR] = (float(*)[SC_STR])(ss + 128 * SC_STR);  // [d][k]
    __shared__ float red[64][4];
    __shared__ float scl[64];

    const int tid = threadIdx.x;

    // ---- load tiles (transposed) ----
    for (int lin = tid; lin < 64 * 128; lin += 256) {
        int r = lin >> 7, d = lin & 127;
        qs[d][r] = g_q_repr[((size_t)(b * LQ_ + r) << 7) + d];
        ps[d][r] = g_pool  [((size_t)(b * KPAD + k0 + r) << 7) + d];
    }
    __syncthreads();

    // ---- normalize cluster columns ----
    {
        const int col = tid & 63;
        const int qu  = tid >> 6;           // 0..3 -> d range qu*32..+31
        float s = 0.0f;
        #pragma unroll
        for (int d = 0; d < 32; d++) {
            float v = ps[qu * 32 + d][col];
            s = fmaf(v, v, s);
        }
        red[col][qu] = s;
    }
    __syncthreads();
    if (tid < 64) {
        float tot = red[tid][0] + red[tid][1] + red[tid][2] + red[tid][3];
        scl[tid] = 1.0f / fmaxf(sqrtf(tot), 1e-12f);
    }
    __syncthreads();
    {
        const int col = tid & 63;
        const int qu  = tid >> 6;
        float sc = scl[col];
        #pragma unroll
        for (int d = 0; d < 32; d++)
            ps[qu * 32 + d][col] *= sc;
    }
    __syncthreads();

    // ---- 64x64 sim, 4x4 per thread ----
    const int tq = tid >> 4;   // 0..15 -> q rows tq*4..+3
    const int tk = tid & 15;   // 0..15 -> k cols tk*4..+3

    float acc[4][4];
    #pragma unroll
    for (int i = 0; i < 4; i++)
        #pragma unroll
        for (int j = 0; j < 4; j++) acc[i][j] = 0.0f;

    for (int d = 0; d < 128; d++) {
        float4 qv = *(const float4*)&qs[d][tq * 4];
        float4 pv = *(const float4*)&ps[d][tk * 4];
        float qa[4] = {qv.x, qv.y, qv.z, qv.w};
        float pa[4] = {pv.x, pv.y, pv.z, pv.w};
        #pragma unroll
        for (int i = 0; i < 4; i++)
            #pragma unroll
            for (int j = 0; j < 4; j++)
                acc[i][j] = fmaf(qa[i], pa[j], acc[i][j]);
    }

    // ---- per-q max over valid clusters, reduce across the 16 tk lanes ----
    const int kleft = kb - k0;   // >=1
    #pragma unroll
    for (int i = 0; i < 4; i++) {
        float m = -3.4e38f;
        #pragma unroll
        for (int j = 0; j < 4; j++)
            if (tk * 4 + j < kleft) m = fmaxf(m, acc[i][j]);
        #pragma unroll
        for (int o = 1; o < 16; o <<= 1)
            m = fmaxf(m, __shfl_xor_sync(0xffffffffu, m, o));
        if (tk == 0)
            atomicMax(&g_qmax[b * LQ_ + tq * 4 + i], flipf(m));
    }
}

// ======================= final reduction =======================
__global__ void final_kernel(const int* __restrict__ q_mask,
                             float* __restrict__ out) {
    const int b = blockIdx.x;
    const int t = threadIdx.x;
    float v = unflipf(g_qmax[b * LQ_ + t]) * (float)q_mask[b * LQ_ + t];
    for (int o = 16; o; o >>= 1) v += __shfl_down_sync(0xffffffffu, v, o);
    __shared__ float sm[2];
    if ((t & 31) == 0) sm[t >> 5] = v;
    __syncthreads();
    if (t == 0) out[b] = sm[0] + sm[1];
}

// ======================= launch =======================
extern "C" void kernel_launch(void* const* d_in, const int* in_sizes, int n_in,
                              void* d_out, int out_size) {
    const float* q_hidden = (const float*)d_in[0];
    const float* d_hidden = (const float*)d_in[1];
    const float* Wm       = (const float*)d_in[2];
    const float* bias     = (const float*)d_in[3];
    const int*   q_mask   = (const int*)  d_in[4];
    const int*   d_mask   = (const int*)  d_in[5];
    const int*   labels   = (const int*)  d_in[6];
    const int*   pf       = (const int*)  d_in[7];
    float*       out      = (float*)d_out;

    cudaFuncSetAttribute(encode_kernel,
                         cudaFuncAttributeMaxDynamicSharedMemorySize, SMEM_DYN);
    cudaFuncSetAttribute(score_kernel,
                         cudaFuncAttributeMaxDynamicSharedMemorySize, SC_SMEM);

    prep_kernel<<<2064, 256>>>(Wm, d_mask, pf);
    encode_kernel<<<QBLK + DBLK, 256, SMEM_DYN>>>(q_hidden, d_hidden, bias,
                                                  q_mask, d_mask, labels);
    dim3 sg(KPAD / 64, B_);
    score_kernel<<<sg, 256, SC_SMEM>>>();
    final_kernel<<<B_, 64>>>(q_mask, out);
}